// round 5
// baseline (speedup 1.0000x reference)
#include <cuda_runtime.h>
#include <math.h>

#define BB 8
#define NN 2000
#define CC 81
#define NPAD 2048
#define METAS 93
#define MAXI 100
#define NTHREADS 1024

typedef unsigned long long u64;

// -------- per-ROI scratch written by kernel1, read by kernel2 --------
__device__ float4 g_obox[BB * NN];   // class-offset box (for NMS)
__device__ float4 g_rbox[BB * NN];   // refined+clipped box (for output)
__device__ float  g_score[BB * NN];  // score, or -1 if invalid
__device__ int    g_cls[BB * NN];

// -------- kernel2 dynamic smem layout (bytes) --------
#define OFF_KEYS   0        // u64[2048]   16384
#define OFF_KEPT   16384    // u64[2048]   16384 -> 32768
#define OFF_OBOX   32768    // float4[2048]32768 -> 65536
#define OFF_SCORE  65536    // float[2048]  8192 -> 73728
#define OFF_CLS    73728    // uchar[2048]  2048 -> 75776
#define OFF_KEEP   75776    // uchar[2048]  2048 -> 77824
#define OFF_CNT    77824    // int[84]       336 -> 78160
#define OFF_BASE   78160    // int[84]       336 -> 78496
#define OFF_CUR    78496    // int[84]       336 -> 78832
#define OFF_STATS  78832    // int[8]         32 -> 78864
#define SMEM_BYTES 78864

// ================= Kernel 1: one warp per ROI, full chip =================
__global__ void __launch_bounds__(256)
prep_kernel(const float* __restrict__ rois,
            const float* __restrict__ probs,
            const float* __restrict__ bbox,
            const float* __restrict__ meta) {
    const int lane = threadIdx.x & 31;
    const int warp = threadIdx.x >> 5;
    const int roi = blockIdx.x * 8 + warp;   // 8 warps/block
    if (roi >= BB * NN) return;
    const int b = roi / NN;

    // ---- warp-cooperative argmax over 81 classes (first-max tie-break) ----
    const float* pr = probs + (size_t)roi * CC;
    float best = -1.0f;
    int bidx = CC;
#pragma unroll
    for (int k = 0; k < 3; k++) {
        int c = lane + 32 * k;
        if (c < CC) {
            float p = pr[c];
            if (p > best) { best = p; bidx = c; }  // per-lane idx increases: strict > = first max
        }
    }
#pragma unroll
    for (int d = 16; d > 0; d >>= 1) {
        float ob = __shfl_xor_sync(0xffffffffu, best, d);
        int oi = __shfl_xor_sync(0xffffffffu, bidx, d);
        if (ob > best || (ob == best && oi < bidx)) { best = ob; bidx = oi; }
    }

    if (lane == 0) {
        const int cls = bidx;
        const float score = best;

        float ih = meta[4];
        float iw = meta[5];
        float sy = __fsub_rn(ih, 1.0f);
        float sx = __fsub_rn(iw, 1.0f);
        const float* mb = meta + (size_t)b * METAS;
        float wy1 = __fsub_rn(mb[7], 0.0f) / sy;
        float wx1 = __fsub_rn(mb[8], 0.0f) / sx;
        float wy2 = __fsub_rn(mb[9], 1.0f) / sy;
        float wx2 = __fsub_rn(mb[10], 1.0f) / sx;

        // refine + clip (exact reference ops, no FMA contraction)
        float4 rv = ((const float4*)rois)[roi];
        float4 dv = ((const float4*)bbox)[(size_t)roi * CC + cls];
        float dy = __fmul_rn(dv.x, 0.1f);
        float dx = __fmul_rn(dv.y, 0.1f);
        float dh = __fmul_rn(dv.z, 0.2f);
        float dw = __fmul_rn(dv.w, 0.2f);
        float h = __fsub_rn(rv.z, rv.x);
        float w = __fsub_rn(rv.w, rv.y);
        float cy = __fadd_rn(__fadd_rn(rv.x, __fmul_rn(0.5f, h)), __fmul_rn(dy, h));
        float cx = __fadd_rn(__fadd_rn(rv.y, __fmul_rn(0.5f, w)), __fmul_rn(dx, w));
        float nh = __fmul_rn(h, expf(dh));
        float nw = __fmul_rn(w, expf(dw));
        float oy1 = fminf(fmaxf(__fsub_rn(cy, __fmul_rn(0.5f, nh)), wy1), wy2);
        float ox1 = fminf(fmaxf(__fsub_rn(cx, __fmul_rn(0.5f, nw)), wx1), wx2);
        float oy2 = fminf(fmaxf(__fadd_rn(cy, __fmul_rn(0.5f, nh)), wy1), wy2);
        float ox2 = fminf(fmaxf(__fadd_rn(cx, __fmul_rn(0.5f, nw)), wx1), wx2);

        float off = __fmul_rn(4.0f, (float)cls);
        g_rbox[roi] = make_float4(oy1, ox1, oy2, ox2);
        g_obox[roi] = make_float4(__fadd_rn(oy1, off), __fadd_rn(ox1, off),
                                  __fadd_rn(oy2, off), __fadd_rn(ox2, off));
        g_cls[roi] = cls;
        bool valid = (cls > 0) && (score >= 0.7f);
        g_score[roi] = valid ? score : -1.0f;
    }
}

// ============ Kernel 2: class-bucket NMS (no sort) + rank select ============
__global__ void __launch_bounds__(NTHREADS, 1)
select_kernel(float* __restrict__ out) {
    extern __shared__ unsigned char dsm[];
    u64* s_keys = (u64*)(dsm + OFF_KEYS);
    u64* s_kept = (u64*)(dsm + OFF_KEPT);
    float4* s_obox = (float4*)(dsm + OFF_OBOX);
    float* s_score = (float*)(dsm + OFF_SCORE);
    unsigned char* s_cls = (unsigned char*)(dsm + OFF_CLS);
    unsigned char* s_keep = (unsigned char*)(dsm + OFF_KEEP);
    int* s_cnt = (int*)(dsm + OFF_CNT);
    int* s_base = (int*)(dsm + OFF_BASE);
    int* s_cur = (int*)(dsm + OFF_CUR);
    int* s_stats = (int*)(dsm + OFF_STATS);

    const int tid = threadIdx.x;
    const int lane = tid & 31;
    const int warp = tid >> 5;
    const int b = blockIdx.x;

    // init
    if (tid < CC) { s_cnt[tid] = 0; s_cur[tid] = 0; }
    if (tid == 0) s_stats[1] = 0;
    for (int n = tid; n < NPAD; n += NTHREADS) s_keep[n] = 1;
    __syncthreads();

    // ---------- Phase A: load records (coalesced), count per class ----------
    for (int n = tid; n < NN; n += NTHREADS) {
        int base = b * NN + n;
        s_obox[n] = g_obox[base];
        int c = g_cls[base];
        s_cls[n] = (unsigned char)c;
        float score = g_score[base];
        s_score[n] = score;
        if (score > 0.0f) atomicAdd(&s_cnt[c], 1);
    }
    __syncthreads();

    // ---------- Phase B: serial prefix over 81 classes ----------
    if (tid == 0) {
        int run = 0;
        for (int c = 0; c < CC; c++) { s_base[c] = run; run += s_cnt[c]; }
    }
    __syncthreads();

    // ---------- Phase C: scatter keys into class buckets ----------
    for (int n = tid; n < NN; n += NTHREADS) {
        float score = s_score[n];
        if (score > 0.0f) {
            int c = s_cls[n];
            int pos = s_base[c] + atomicAdd(&s_cur[c], 1);
            unsigned int sb = __float_as_uint(score);
            s_keys[pos] = ((u64)sb << 11) | (u64)(2047 - n);   // score desc, idx asc
        }
    }
    __syncthreads();

    // ---------- Phase D: per-class fused max-select greedy NMS (one warp/class) ----------
    // Cross-class IoU is exactly 0 (class offset 4*cls, boxes in [0,1]), so the
    // global greedy NMS decomposes into independent per-class greedy NMS.
    for (int c = warp; c < CC; c += 32) {
        const int base = s_base[c];
        const int L = s_cnt[c];
        int keptc = 0;
        while (true) {
            // warp-max over active entries (keys are never 0 for real entries)
            u64 mk = 0ull; int mp = -1;
            for (int t = lane; t < L; t += 32) {
                int p = base + t;
                if (s_keep[p] == 1) {
                    u64 k = s_keys[p];
                    if (k > mk) { mk = k; mp = p; }
                }
            }
#pragma unroll
            for (int d = 16; d > 0; d >>= 1) {
                u64 ok = __shfl_xor_sync(0xffffffffu, mk, d);
                int op = __shfl_xor_sync(0xffffffffu, mp, d);
                if (ok > mk) { mk = ok; mp = op; }
            }
            if (mk == 0ull) break;
            if (lane == 0) {
                s_keep[mp] = 2;   // kept/processed
                if (keptc < MAXI) {
                    int kp = atomicAdd(&s_stats[1], 1);
                    s_kept[kp] = mk;
                }
            }
            keptc++;
            __syncwarp();
            int orig = 2047 - (int)(mk & 2047ull);
            float4 bi = s_obox[orig];
            float ai = __fmul_rn(__fsub_rn(bi.z, bi.x), __fsub_rn(bi.w, bi.y));
            for (int t = lane; t < L; t += 32) {
                int p = base + t;
                if (s_keep[p] == 1) {
                    int oj = 2047 - (int)(s_keys[p] & 2047ull);
                    float4 bj = s_obox[oj];
                    float iy = fmaxf(0.0f, __fsub_rn(fminf(bi.z, bj.z), fmaxf(bi.x, bj.x)));
                    float ix = fmaxf(0.0f, __fsub_rn(fminf(bi.w, bj.w), fmaxf(bi.y, bj.y)));
                    float inter = __fmul_rn(iy, ix);
                    float aj = __fmul_rn(__fsub_rn(bj.z, bj.x), __fsub_rn(bj.w, bj.y));
                    float den = __fadd_rn(__fsub_rn(__fadd_rn(ai, aj), inter), 1e-12f);
                    if (inter / den > 0.3f) s_keep[p] = 0;
                }
            }
            __syncwarp();
        }
    }
    __syncthreads();
    const int K = s_stats[1];

    // ---------- Phase E: zero output, then rank-select top-100 ----------
    float* ob = out + (size_t)b * MAXI * 6;
    for (int x = tid; x < MAXI * 6; x += NTHREADS) ob[x] = 0.0f;
    __syncthreads();

    for (int i = tid; i < K; i += NTHREADS) {
        u64 kk = s_kept[i];
        int r = 0;
        for (int j = 0; j < K; j++) r += (s_kept[j] > kk) ? 1 : 0;   // keys unique
        if (r < MAXI) {
            int orig = 2047 - (int)(kk & 2047ull);
            float4 rb = g_rbox[b * NN + orig];
            float* o = ob + r * 6;
            o[0] = rb.x; o[1] = rb.y; o[2] = rb.z; o[3] = rb.w;
            o[4] = (float)s_cls[orig];
            o[5] = __uint_as_float((unsigned int)(kk >> 11));
        }
    }
}

extern "C" void kernel_launch(void* const* d_in, const int* in_sizes, int n_in,
                              void* d_out, int out_size) {
    const float* rois  = (const float*)d_in[0];
    const float* probs = (const float*)d_in[1];
    const float* bbox  = (const float*)d_in[2];
    const float* meta  = (const float*)d_in[3];
    float* out = (float*)d_out;

    cudaFuncSetAttribute(select_kernel,
                         cudaFuncAttributeMaxDynamicSharedMemorySize, SMEM_BYTES);

    prep_kernel<<<(BB * NN + 7) / 8, 256>>>(rois, probs, bbox, meta);
    select_kernel<<<BB, NTHREADS, SMEM_BYTES>>>(out);
}

// round 7
// speedup vs baseline: 1.3689x; 1.3689x over previous
#include <cuda_runtime.h>
#include <math.h>

#define BB 8
#define NN 2000
#define CC 81
#define NPAD 2048
#define METAS 93
#define MAXI 100
#define NTHREADS 1024
#define FULLM 0xffffffffu

typedef unsigned long long u64;

// -------- per-ROI scratch written by kernel1, read by kernel2 --------
__device__ float4 g_obox[BB * NN];   // class-offset box (for NMS)
__device__ float4 g_rbox[BB * NN];   // refined+clipped box (for output)
__device__ float  g_score[BB * NN];  // score, or -1 if invalid
__device__ int    g_cls[BB * NN];

// -------- kernel2 dynamic smem layout (bytes) --------
#define OFF_KEYS   0        // u64[2048]    16384
#define OFF_KEPT   16384    // u64[2048]    16384 -> 32768
#define OFF_OBOX   32768    // float4[2048] 32768 -> 65536
#define OFF_SCORE  65536    // float[2048]   8192 -> 73728
#define OFF_CLS    73728    // uchar[2048]   2048 -> 75776
#define OFF_KEEP   75776    // uchar[2048]   2048 -> 77824
#define OFF_CNT    77824    // int[96]        384 -> 78208
#define OFF_BASE   78208    // int[96]        384 -> 78592
#define OFF_CUR    78592    // int[96]        384 -> 78976
#define OFF_STATS  78976    // int[8]          32 -> 79008
#define SMEM_BYTES 79008

// ================= Kernel 1: one warp per ROI, full chip =================
__global__ void __launch_bounds__(256)
prep_kernel(const float* __restrict__ rois,
            const float* __restrict__ probs,
            const float* __restrict__ bbox,
            const float* __restrict__ meta) {
    const int lane = threadIdx.x & 31;
    const int warp = threadIdx.x >> 5;
    const int roi = blockIdx.x * 8 + warp;   // 8 warps/block
    if (roi >= BB * NN) return;
    const int b = roi / NN;

    // ---- warp-cooperative argmax over 81 classes (first-max tie-break) ----
    const float* pr = probs + (size_t)roi * CC;
    float best = -1.0f;
    int bidx = CC;
#pragma unroll
    for (int k = 0; k < 3; k++) {
        int c = lane + 32 * k;
        if (c < CC) {
            float p = pr[c];
            if (p > best) { best = p; bidx = c; }  // per-lane idx increases: strict > = first max
        }
    }
#pragma unroll
    for (int d = 16; d > 0; d >>= 1) {
        float ob = __shfl_xor_sync(FULLM, best, d);
        int oi = __shfl_xor_sync(FULLM, bidx, d);
        if (ob > best || (ob == best && oi < bidx)) { best = ob; bidx = oi; }
    }

    if (lane == 0) {
        const int cls = bidx;
        const float score = best;

        float ih = meta[4];
        float iw = meta[5];
        float sy = __fsub_rn(ih, 1.0f);
        float sx = __fsub_rn(iw, 1.0f);
        const float* mb = meta + (size_t)b * METAS;
        float wy1 = __fsub_rn(mb[7], 0.0f) / sy;
        float wx1 = __fsub_rn(mb[8], 0.0f) / sx;
        float wy2 = __fsub_rn(mb[9], 1.0f) / sy;
        float wx2 = __fsub_rn(mb[10], 1.0f) / sx;

        // refine + clip (exact reference ops, no FMA contraction)
        float4 rv = ((const float4*)rois)[roi];
        float4 dv = ((const float4*)bbox)[(size_t)roi * CC + cls];
        float dy = __fmul_rn(dv.x, 0.1f);
        float dx = __fmul_rn(dv.y, 0.1f);
        float dh = __fmul_rn(dv.z, 0.2f);
        float dw = __fmul_rn(dv.w, 0.2f);
        float h = __fsub_rn(rv.z, rv.x);
        float w = __fsub_rn(rv.w, rv.y);
        float cy = __fadd_rn(__fadd_rn(rv.x, __fmul_rn(0.5f, h)), __fmul_rn(dy, h));
        float cx = __fadd_rn(__fadd_rn(rv.y, __fmul_rn(0.5f, w)), __fmul_rn(dx, w));
        float nh = __fmul_rn(h, expf(dh));
        float nw = __fmul_rn(w, expf(dw));
        float oy1 = fminf(fmaxf(__fsub_rn(cy, __fmul_rn(0.5f, nh)), wy1), wy2);
        float ox1 = fminf(fmaxf(__fsub_rn(cx, __fmul_rn(0.5f, nw)), wx1), wx2);
        float oy2 = fminf(fmaxf(__fadd_rn(cy, __fmul_rn(0.5f, nh)), wy1), wy2);
        float ox2 = fminf(fmaxf(__fadd_rn(cx, __fmul_rn(0.5f, nw)), wx1), wx2);

        float off = __fmul_rn(4.0f, (float)cls);
        g_rbox[roi] = make_float4(oy1, ox1, oy2, ox2);
        g_obox[roi] = make_float4(__fadd_rn(oy1, off), __fadd_rn(ox1, off),
                                  __fadd_rn(oy2, off), __fadd_rn(ox2, off));
        g_cls[roi] = cls;
        bool valid = (cls > 0) && (score >= 0.7f);
        g_score[roi] = valid ? score : -1.0f;
    }
}

__device__ __forceinline__ float iou_ref(float4 bi, float ai, float4 bj) {
    float iy = fmaxf(0.0f, __fsub_rn(fminf(bi.z, bj.z), fmaxf(bi.x, bj.x)));
    float ix = fmaxf(0.0f, __fsub_rn(fminf(bi.w, bj.w), fmaxf(bi.y, bj.y)));
    float inter = __fmul_rn(iy, ix);
    float aj = __fmul_rn(__fsub_rn(bj.z, bj.x), __fsub_rn(bj.w, bj.y));
    float den = __fadd_rn(__fsub_rn(__fadd_rn(ai, aj), inter), 1e-12f);
    return inter / den;
}

// ========== Kernel 2: class buckets + warp-register NMS + rank select ==========
__global__ void __launch_bounds__(NTHREADS, 1)
select_kernel(float* __restrict__ out) {
    extern __shared__ unsigned char dsm[];
    u64* s_keys = (u64*)(dsm + OFF_KEYS);
    u64* s_kept = (u64*)(dsm + OFF_KEPT);
    float4* s_obox = (float4*)(dsm + OFF_OBOX);
    float* s_score = (float*)(dsm + OFF_SCORE);
    unsigned char* s_cls = (unsigned char*)(dsm + OFF_CLS);
    unsigned char* s_keep = (unsigned char*)(dsm + OFF_KEEP);
    int* s_cnt = (int*)(dsm + OFF_CNT);
    int* s_base = (int*)(dsm + OFF_BASE);
    int* s_cur = (int*)(dsm + OFF_CUR);
    int* s_stats = (int*)(dsm + OFF_STATS);

    const int tid = threadIdx.x;
    const int lane = tid & 31;
    const int warp = tid >> 5;
    const int b = blockIdx.x;

    if (tid < 96) { s_cnt[tid] = 0; s_cur[tid] = 0; }
    if (tid == 0) s_stats[1] = 0;
    __syncthreads();

    // ---------- Phase A: load records (coalesced), count per class ----------
    for (int n = tid; n < NN; n += NTHREADS) {
        int base = b * NN + n;
        s_obox[n] = g_obox[base];
        int c = g_cls[base];
        s_cls[n] = (unsigned char)c;
        float score = g_score[base];
        s_score[n] = score;
        if (score > 0.0f) atomicAdd(&s_cnt[c], 1);
    }
    __syncthreads();

    // ---------- Phase B: warp-0 shfl prefix over 81 classes ----------
    if (warp == 0) {
        int run = 0;
        for (int cb = 0; cb < CC; cb += 32) {
            int c = cb + lane;
            int v = (c < CC) ? s_cnt[c] : 0;
            int inc = v;
#pragma unroll
            for (int d = 1; d < 32; d <<= 1) {
                int u = __shfl_up_sync(FULLM, inc, d);
                if (lane >= d) inc += u;
            }
            if (c < CC) s_base[c] = run + inc - v;
            run += __shfl_sync(FULLM, inc, 31);
        }
    }
    __syncthreads();

    // ---------- Phase C: scatter keys into class buckets ----------
    for (int n = tid; n < NN; n += NTHREADS) {
        float score = s_score[n];
        if (score > 0.0f) {
            int c = s_cls[n];
            int pos = s_base[c] + atomicAdd(&s_cur[c], 1);
            unsigned int sb = __float_as_uint(score);
            s_keys[pos] = ((u64)sb << 11) | (u64)(2047 - n);   // score desc, idx asc
            s_keep[pos] = 1;
        }
    }
    __syncthreads();

    // ---------- Phase D: per-class NMS, one warp per class ----------
    // Cross-class IoU is exactly 0 (class offset 4*cls, boxes in [0,1]), so the
    // global greedy NMS decomposes into independent per-class greedy NMS, and
    // the per-class rank cap folds into a kept counter.
    for (int c = warp; c < CC; c += 32) {
        const int base = s_base[c];
        const int L = s_cnt[c];
        if (L == 0) continue;

        if (L <= 32) {
            // ---- register path: 1 key per lane, shfl bitonic, ballot greedy ----
            u64 key = (lane < L) ? s_keys[base + lane] : 0ull;
            // ascending bitonic on ~key == descending on key; pads (~0) go last
            u64 v = ~key;
#pragma unroll
            for (int k = 2; k <= 32; k <<= 1) {
#pragma unroll
                for (int j = k >> 1; j > 0; j >>= 1) {
                    u64 x = __shfl_xor_sync(FULLM, v, j);
                    bool dir = ((lane & k) == 0);
                    bool lower = ((lane & j) == 0);
                    u64 mn = (v < x) ? v : x;
                    u64 mx = (v < x) ? x : v;
                    v = (dir == lower) ? mn : mx;
                }
            }
            key = ~v;   // lane i holds i-th largest key; lanes >= L hold 0

            float4 bx = make_float4(0.f, 0.f, 0.f, 0.f);
            float ar = 0.f;
            if (key != 0ull) {
                int orig = 2047 - (int)(key & 2047ull);
                bx = s_obox[orig];
                ar = __fmul_rn(__fsub_rn(bx.z, bx.x), __fsub_rn(bx.w, bx.y));
            }
            unsigned int alive = __ballot_sync(FULLM, key != 0ull);
            int keptc = 0;
            while (alive) {
                int a = __ffs(alive) - 1;                 // max remaining (sorted)
                u64 mk = __shfl_sync(FULLM, key, a);
                float4 bi;
                bi.x = __shfl_sync(FULLM, bx.x, a);
                bi.y = __shfl_sync(FULLM, bx.y, a);
                bi.z = __shfl_sync(FULLM, bx.z, a);
                bi.w = __shfl_sync(FULLM, bx.w, a);
                float ai = __shfl_sync(FULLM, ar, a);
                bool sup = false;
                if (((alive >> lane) & 1u) && lane > a)
                    sup = iou_ref(bi, ai, bx) > 0.3f;
                unsigned int supm = __ballot_sync(FULLM, sup);
                alive &= ~supm;
                alive &= ~(1u << a);
                if (lane == 0 && keptc < MAXI) {
                    int kp = atomicAdd(&s_stats[1], 1);
                    s_kept[kp] = mk;
                }
                keptc++;
            }
        } else {
            // ---- rare fallback: in-place odd-even sort + linear greedy ----
            for (int pass = 0; pass < L; pass++) {
                int start = pass & 1;
                for (int idx = start + 2 * lane; idx + 1 < L; idx += 64) {
                    u64 a = s_keys[base + idx], b2 = s_keys[base + idx + 1];
                    if (b2 > a) { s_keys[base + idx] = b2; s_keys[base + idx + 1] = a; }
                }
                __syncwarp();
            }
            int keptc = 0;
            for (int a = 0; a < L; a++) {
                if (s_keep[base + a]) {
                    u64 mk = s_keys[base + a];
                    int orig = 2047 - (int)(mk & 2047ull);
                    float4 bi = s_obox[orig];
                    float ai = __fmul_rn(__fsub_rn(bi.z, bi.x), __fsub_rn(bi.w, bi.y));
                    for (int t = a + 1 + lane; t < L; t += 32) {
                        if (s_keep[base + t]) {
                            int oj = 2047 - (int)(s_keys[base + t] & 2047ull);
                            if (iou_ref(bi, ai, s_obox[oj]) > 0.3f) s_keep[base + t] = 0;
                        }
                    }
                    if (lane == 0 && keptc < MAXI) {
                        int kp = atomicAdd(&s_stats[1], 1);
                        s_kept[kp] = mk;
                    }
                    keptc++;
                }
                __syncwarp();
            }
        }
    }
    __syncthreads();
    const int K = s_stats[1];

    // ---------- Phase E: zero output, then rank-select top-100 ----------
    float* ob = out + (size_t)b * MAXI * 6;
    for (int x = tid; x < MAXI * 6; x += NTHREADS) ob[x] = 0.0f;
    __syncthreads();

    for (int i = tid; i < K; i += NTHREADS) {
        u64 kk = s_kept[i];
        int r = 0;
        int j = 0;
#pragma unroll 4
        for (; j + 4 <= K; j += 4) {
            r += (s_kept[j] > kk) ? 1 : 0;
            r += (s_kept[j + 1] > kk) ? 1 : 0;
            r += (s_kept[j + 2] > kk) ? 1 : 0;
            r += (s_kept[j + 3] > kk) ? 1 : 0;
        }
        for (; j < K; j++) r += (s_kept[j] > kk) ? 1 : 0;
        if (r < MAXI) {
            int orig = 2047 - (int)(kk & 2047ull);
            float4 rb = g_rbox[b * NN + orig];
            float* o = ob + r * 6;
            o[0] = rb.x; o[1] = rb.y; o[2] = rb.z; o[3] = rb.w;
            o[4] = (float)s_cls[orig];
            o[5] = __uint_as_float((unsigned int)(kk >> 11));
        }
    }
}

extern "C" void kernel_launch(void* const* d_in, const int* in_sizes, int n_in,
                              void* d_out, int out_size) {
    const float* rois  = (const float*)d_in[0];
    const float* probs = (const float*)d_in[1];
    const float* bbox  = (const float*)d_in[2];
    const float* meta  = (const float*)d_in[3];
    float* out = (float*)d_out;

    cudaFuncSetAttribute(select_kernel,
                         cudaFuncAttributeMaxDynamicSharedMemorySize, SMEM_BYTES);

    prep_kernel<<<(BB * NN + 7) / 8, 256>>>(rois, probs, bbox, meta);
    select_kernel<<<BB, NTHREADS, SMEM_BYTES>>>(out);
}

// round 11
// speedup vs baseline: 1.4264x; 1.0420x over previous
#include <cuda_runtime.h>
#include <math.h>

#define BB 8
#define NN 2000
#define CC 81
#define NPAD 2048
#define METAS 93
#define MAXI 100
#define NTHREADS 1024
#define FULLM 0xffffffffu

typedef unsigned long long u64;

// -------- global scratch --------
__device__ float4 g_obox[BB * NN];   // class-offset box (for NMS)
__device__ float4 g_rbox[BB * NN];   // refined+clipped box (for output)
__device__ float  g_score[BB * NN];  // score, or -1 if invalid
__device__ int    g_cls[BB * NN];
__device__ u64    g_kept[BB * NPAD]; // dense kept keys per image
__device__ int    g_kcnt[BB];

// -------- select_a smem layout (bytes) --------
#define OFF_KEYS   0        // u64[2048]    16384
#define OFF_KEPT   16384    // u64[2048]    16384 -> 32768
#define OFF_OBOX   32768    // float4[2048] 32768 -> 65536
#define OFF_SCORE  65536    // float[2048]   8192 -> 73728
#define OFF_CLS    73728    // uchar[2048]   2048 -> 75776
#define OFF_KEEP   75776    // uchar[2048]   2048 -> 77824
#define OFF_CNT    77824    // int[96]        384 -> 78208
#define OFF_BASE   78208    // int[96]        384 -> 78592
#define OFF_CUR    78592    // int[96]        384 -> 78976
#define OFF_KC     78976    // int[96]        384 -> 79360
#define OFF_KB     79360    // int[96]        384 -> 79744
#define OFF_STATS  79744    // int[8]          32 -> 79776
#define SMEM_BYTES 79776

// ================= Kernel 1: one warp per ROI, full chip =================
__global__ void __launch_bounds__(256)
prep_kernel(const float* __restrict__ rois,
            const float* __restrict__ probs,
            const float* __restrict__ bbox,
            const float* __restrict__ meta) {
    const int lane = threadIdx.x & 31;
    const int warp = threadIdx.x >> 5;
    const int roi = blockIdx.x * 8 + warp;   // 8 warps/block
    if (roi >= BB * NN) return;
    const int b = roi / NN;

    // ---- warp-cooperative argmax over 81 classes (first-max tie-break) ----
    const float* pr = probs + (size_t)roi * CC;
    float best = -1.0f;
    int bidx = CC;
#pragma unroll
    for (int k = 0; k < 3; k++) {
        int c = lane + 32 * k;
        if (c < CC) {
            float p = pr[c];
            if (p > best) { best = p; bidx = c; }  // per-lane idx increases: strict > = first max
        }
    }
#pragma unroll
    for (int d = 16; d > 0; d >>= 1) {
        float ob = __shfl_xor_sync(FULLM, best, d);
        int oi = __shfl_xor_sync(FULLM, bidx, d);
        if (ob > best || (ob == best && oi < bidx)) { best = ob; bidx = oi; }
    }

    if (lane == 0) {
        const int cls = bidx;
        const float score = best;

        float ih = meta[4];
        float iw = meta[5];
        float sy = __fsub_rn(ih, 1.0f);
        float sx = __fsub_rn(iw, 1.0f);
        const float* mb = meta + (size_t)b * METAS;
        float wy1 = __fsub_rn(mb[7], 0.0f) / sy;
        float wx1 = __fsub_rn(mb[8], 0.0f) / sx;
        float wy2 = __fsub_rn(mb[9], 1.0f) / sy;
        float wx2 = __fsub_rn(mb[10], 1.0f) / sx;

        // refine + clip (exact reference ops, no FMA contraction)
        float4 rv = ((const float4*)rois)[roi];
        float4 dv = ((const float4*)bbox)[(size_t)roi * CC + cls];
        float dy = __fmul_rn(dv.x, 0.1f);
        float dx = __fmul_rn(dv.y, 0.1f);
        float dh = __fmul_rn(dv.z, 0.2f);
        float dw = __fmul_rn(dv.w, 0.2f);
        float h = __fsub_rn(rv.z, rv.x);
        float w = __fsub_rn(rv.w, rv.y);
        float cy = __fadd_rn(__fadd_rn(rv.x, __fmul_rn(0.5f, h)), __fmul_rn(dy, h));
        float cx = __fadd_rn(__fadd_rn(rv.y, __fmul_rn(0.5f, w)), __fmul_rn(dx, w));
        float nh = __fmul_rn(h, expf(dh));
        float nw = __fmul_rn(w, expf(dw));
        float oy1 = fminf(fmaxf(__fsub_rn(cy, __fmul_rn(0.5f, nh)), wy1), wy2);
        float ox1 = fminf(fmaxf(__fsub_rn(cx, __fmul_rn(0.5f, nw)), wx1), wx2);
        float oy2 = fminf(fmaxf(__fadd_rn(cy, __fmul_rn(0.5f, nh)), wy1), wy2);
        float ox2 = fminf(fmaxf(__fadd_rn(cx, __fmul_rn(0.5f, nw)), wx1), wx2);

        float off = __fmul_rn(4.0f, (float)cls);
        g_rbox[roi] = make_float4(oy1, ox1, oy2, ox2);
        g_obox[roi] = make_float4(__fadd_rn(oy1, off), __fadd_rn(ox1, off),
                                  __fadd_rn(oy2, off), __fadd_rn(ox2, off));
        g_cls[roi] = cls;
        bool valid = (cls > 0) && (score >= 0.7f);
        g_score[roi] = valid ? score : -1.0f;
    }
}

__device__ __forceinline__ float iou_ref(float4 bi, float ai, float4 bj) {
    float iy = fmaxf(0.0f, __fsub_rn(fminf(bi.z, bj.z), fmaxf(bi.x, bj.x)));
    float ix = fmaxf(0.0f, __fsub_rn(fminf(bi.w, bj.w), fmaxf(bi.y, bj.y)));
    float inter = __fmul_rn(iy, ix);
    float aj = __fmul_rn(__fsub_rn(bj.z, bj.x), __fsub_rn(bj.w, bj.y));
    float den = __fadd_rn(__fsub_rn(__fadd_rn(ai, aj), inter), 1e-12f);
    return inter / den;
}

// ===== Kernel 2a: class buckets + warp NMS -> dense kept list (no atomics in NMS) =====
__global__ void __launch_bounds__(NTHREADS, 1)
select_a(float* __restrict__ dummy) {
    extern __shared__ unsigned char dsm[];
    u64* s_keys = (u64*)(dsm + OFF_KEYS);
    u64* s_kept = (u64*)(dsm + OFF_KEPT);
    float4* s_obox = (float4*)(dsm + OFF_OBOX);
    float* s_score = (float*)(dsm + OFF_SCORE);
    unsigned char* s_cls = (unsigned char*)(dsm + OFF_CLS);
    unsigned char* s_keep = (unsigned char*)(dsm + OFF_KEEP);
    int* s_cnt = (int*)(dsm + OFF_CNT);
    int* s_base = (int*)(dsm + OFF_BASE);
    int* s_cur = (int*)(dsm + OFF_CUR);
    int* s_kc = (int*)(dsm + OFF_KC);
    int* s_kb = (int*)(dsm + OFF_KB);
    int* s_stats = (int*)(dsm + OFF_STATS);

    const int tid = threadIdx.x;
    const int lane = tid & 31;
    const int warp = tid >> 5;
    const int b = blockIdx.x;

    if (tid < 96) { s_cnt[tid] = 0; s_cur[tid] = 0; s_kc[tid] = 0; }
    __syncthreads();

    // ---------- Phase A: load records (coalesced), count per class ----------
    for (int n = tid; n < NN; n += NTHREADS) {
        int base = b * NN + n;
        s_obox[n] = g_obox[base];
        int c = g_cls[base];
        s_cls[n] = (unsigned char)c;
        float score = g_score[base];
        s_score[n] = score;
        if (score > 0.0f) atomicAdd(&s_cnt[c], 1);
    }
    __syncthreads();

    // ---------- Phase B: warp-0 shfl prefix over 81 classes ----------
    if (warp == 0) {
        int run = 0;
        for (int cb = 0; cb < CC; cb += 32) {
            int c = cb + lane;
            int v = (c < CC) ? s_cnt[c] : 0;
            int inc = v;
#pragma unroll
            for (int d = 1; d < 32; d <<= 1) {
                int u = __shfl_up_sync(FULLM, inc, d);
                if (lane >= d) inc += u;
            }
            if (c < CC) s_base[c] = run + inc - v;
            run += __shfl_sync(FULLM, inc, 31);
        }
    }
    __syncthreads();

    // ---------- Phase C: scatter keys into class buckets ----------
    for (int n = tid; n < NN; n += NTHREADS) {
        float score = s_score[n];
        if (score > 0.0f) {
            int c = s_cls[n];
            int pos = s_base[c] + atomicAdd(&s_cur[c], 1);
            unsigned int sb = __float_as_uint(score);
            s_keys[pos] = ((u64)sb << 11) | (u64)(2047 - n);   // score desc, idx asc
            s_keep[pos] = 1;
        }
    }
    __syncthreads();

    // ---------- Phase D: per-class NMS, one warp per class (atomic-free) ----------
    // Cross-class IoU is exactly 0 (class offset 4*cls, boxes in [0,1]), so the
    // global greedy NMS decomposes into independent per-class greedy NMS, and
    // the per-class rank cap folds into a kept counter.
    for (int c = warp; c < CC; c += 32) {
        const int base = s_base[c];
        const int L = s_cnt[c];
        if (L == 0) continue;
        int keptc = 0;

        if (L <= 32) {
            // ---- register path: 1 key per lane, shfl bitonic, ballot greedy ----
            u64 key = (lane < L) ? s_keys[base + lane] : 0ull;
            u64 v = ~key;   // ascending on ~key == descending on key; pads last
#pragma unroll
            for (int k = 2; k <= 32; k <<= 1) {
#pragma unroll
                for (int j = k >> 1; j > 0; j >>= 1) {
                    u64 x = __shfl_xor_sync(FULLM, v, j);
                    bool dir = ((lane & k) == 0);
                    bool lower = ((lane & j) == 0);
                    u64 mn = (v < x) ? v : x;
                    u64 mx = (v < x) ? x : v;
                    v = (dir == lower) ? mn : mx;
                }
            }
            key = ~v;   // lane i holds i-th largest key; lanes >= L hold 0

            float4 bx = make_float4(0.f, 0.f, 0.f, 0.f);
            float ar = 0.f;
            if (key != 0ull) {
                int orig = 2047 - (int)(key & 2047ull);
                bx = s_obox[orig];
                ar = __fmul_rn(__fsub_rn(bx.z, bx.x), __fsub_rn(bx.w, bx.y));
            }
            unsigned int alive = __ballot_sync(FULLM, key != 0ull);
            while (alive) {
                int a = __ffs(alive) - 1;                 // max remaining (sorted)
                u64 mk = __shfl_sync(FULLM, key, a);
                // broadcast box via LDS instead of 5 shfls
                int oi = 2047 - (int)(mk & 2047ull);
                float4 bi = s_obox[oi];
                float ai = __fmul_rn(__fsub_rn(bi.z, bi.x), __fsub_rn(bi.w, bi.y));
                bool sup = false;
                if (((alive >> lane) & 1u) && lane > a)
                    sup = iou_ref(bi, ai, bx) > 0.3f;
                unsigned int supm = __ballot_sync(FULLM, sup);
                alive &= ~supm;
                alive &= ~(1u << a);
                if (lane == 0 && keptc < MAXI) s_kept[base + keptc] = mk;
                keptc++;
            }
        } else {
            // ---- rare fallback: in-place odd-even sort + linear greedy ----
            for (int pass = 0; pass < L; pass++) {
                int start = pass & 1;
                for (int idx = start + 2 * lane; idx + 1 < L; idx += 64) {
                    u64 a = s_keys[base + idx], b2 = s_keys[base + idx + 1];
                    if (b2 > a) { s_keys[base + idx] = b2; s_keys[base + idx + 1] = a; }
                }
                __syncwarp();
            }
            for (int a = 0; a < L; a++) {
                if (s_keep[base + a]) {
                    u64 mk = s_keys[base + a];
                    int orig = 2047 - (int)(mk & 2047ull);
                    float4 bi = s_obox[orig];
                    float ai = __fmul_rn(__fsub_rn(bi.z, bi.x), __fsub_rn(bi.w, bi.y));
                    for (int t = a + 1 + lane; t < L; t += 32) {
                        if (s_keep[base + t]) {
                            int oj = 2047 - (int)(s_keys[base + t] & 2047ull);
                            if (iou_ref(bi, ai, s_obox[oj]) > 0.3f) s_keep[base + t] = 0;
                        }
                    }
                    if (lane == 0 && keptc < MAXI) s_kept[base + keptc] = mk;
                    keptc++;
                }
                __syncwarp();
            }
        }
        if (lane == 0) s_kc[c] = (keptc < MAXI) ? keptc : MAXI;
    }
    __syncthreads();

    // ---------- Phase D2: prefix over per-class kept counts ----------
    if (warp == 0) {
        int run = 0;
        for (int cb = 0; cb < CC; cb += 32) {
            int c = cb + lane;
            int v = (c < CC) ? s_kc[c] : 0;
            int inc = v;
#pragma unroll
            for (int d = 1; d < 32; d <<= 1) {
                int u = __shfl_up_sync(FULLM, inc, d);
                if (lane >= d) inc += u;
            }
            if (c < CC) s_kb[c] = run + inc - v;
            run += __shfl_sync(FULLM, inc, 31);
        }
        if (lane == 0) s_stats[0] = run;
    }
    __syncthreads();

    // ---------- Phase D3: compact kept keys to global dense list ----------
    u64* gk = g_kept + (size_t)b * NPAD;
    for (int c = warp; c < CC; c += 32) {
        int kc = s_kc[c];
        int base = s_base[c];
        int kb = s_kb[c];
        for (int t = lane; t < kc; t += 32)
            gk[kb + t] = s_kept[base + t];
    }
    if (tid == 0) g_kcnt[b] = s_stats[0];
}

// ===== Kernel 2b: rank-select top-100 + write output =====
__global__ void __launch_bounds__(NTHREADS, 1)
select_b(float* __restrict__ out) {
    __shared__ u64 sk[NPAD];
    const int tid = threadIdx.x;
    const int b = blockIdx.x;
    const int K = g_kcnt[b];

    const u64* gk = g_kept + (size_t)b * NPAD;
    for (int i = tid; i < K; i += NTHREADS) sk[i] = gk[i];

    float* ob = out + (size_t)b * MAXI * 6;
    for (int x = tid; x < MAXI * 6; x += NTHREADS) ob[x] = 0.0f;
    __syncthreads();

    for (int i = tid; i < K; i += NTHREADS) {
        u64 kk = sk[i];
        int r = 0;
        int j = 0;
#pragma unroll 8
        for (; j + 8 <= K; j += 8) {
            r += (sk[j] > kk);     r += (sk[j + 1] > kk);
            r += (sk[j + 2] > kk); r += (sk[j + 3] > kk);
            r += (sk[j + 4] > kk); r += (sk[j + 5] > kk);
            r += (sk[j + 6] > kk); r += (sk[j + 7] > kk);
        }
        for (; j < K; j++) r += (sk[j] > kk);
        if (r < MAXI) {
            int orig = 2047 - (int)(kk & 2047ull);
            float4 rb = g_rbox[b * NN + orig];
            float* o = ob + r * 6;
            o[0] = rb.x; o[1] = rb.y; o[2] = rb.z; o[3] = rb.w;
            o[4] = (float)g_cls[b * NN + orig];
            o[5] = __uint_as_float((unsigned int)(kk >> 11));
        }
    }
}

extern "C" void kernel_launch(void* const* d_in, const int* in_sizes, int n_in,
                              void* d_out, int out_size) {
    const float* rois  = (const float*)d_in[0];
    const float* probs = (const float*)d_in[1];
    const float* bbox  = (const float*)d_in[2];
    const float* meta  = (const float*)d_in[3];
    float* out = (float*)d_out;

    cudaFuncSetAttribute(select_a,
                         cudaFuncAttributeMaxDynamicSharedMemorySize, SMEM_BYTES);

    prep_kernel<<<(BB * NN + 7) / 8, 256>>>(rois, probs, bbox, meta);
    select_a<<<BB, NTHREADS, SMEM_BYTES>>>(out);
    select_b<<<BB, NTHREADS>>>(out);
}

// round 12
// speedup vs baseline: 1.6627x; 1.1657x over previous
#include <cuda_runtime.h>
#include <math.h>

#define BB 8
#define NN 2000
#define CC 81
#define METAS 93
#define MAXI 100
#define BCAP 2048
#define NBKT (BB * CC)
#define FULLM 0xffffffffu

typedef unsigned long long u64;
#define SUPBIT 0x8000000000000000ull

// -------- global scratch --------
__device__ float4 g_obox[BB * NN];            // class-offset box (for NMS)
__device__ float4 g_rbox[BB * NN];            // refined+clipped box (for output)
__device__ int    g_cls[BB * NN];             // argmax class per ROI
__device__ int    g_bcnt[NBKT];               // per-(image,class) bucket count
__device__ u64    g_bucket[(size_t)NBKT * BCAP];   // per-(image,class) keys
__device__ u64    g_keptbc[(size_t)NBKT * 128];    // kept keys per bucket (<=100)
__device__ int    g_kc[NBKT];                 // kept count per bucket

// ================= Kernel 1: one warp per ROI, full chip + bucket scatter =================
__global__ void __launch_bounds__(256)
prep_kernel(const float* __restrict__ rois,
            const float* __restrict__ probs,
            const float* __restrict__ bbox,
            const float* __restrict__ meta) {
    const int lane = threadIdx.x & 31;
    const int warp = threadIdx.x >> 5;
    const int roi = blockIdx.x * 8 + warp;   // 8 warps/block
    if (roi >= BB * NN) return;
    const int b = roi / NN;
    const int n = roi - b * NN;

    // ---- warp-cooperative argmax over 81 classes (first-max tie-break) ----
    const float* pr = probs + (size_t)roi * CC;
    float best = -1.0f;
    int bidx = CC;
#pragma unroll
    for (int k = 0; k < 3; k++) {
        int c = lane + 32 * k;
        if (c < CC) {
            float p = pr[c];
            if (p > best) { best = p; bidx = c; }  // per-lane idx increases: strict > = first max
        }
    }
#pragma unroll
    for (int d = 16; d > 0; d >>= 1) {
        float ob = __shfl_xor_sync(FULLM, best, d);
        int oi = __shfl_xor_sync(FULLM, bidx, d);
        if (ob > best || (ob == best && oi < bidx)) { best = ob; bidx = oi; }
    }

    if (lane == 0) {
        const int cls = bidx;
        const float score = best;

        float ih = meta[4];
        float iw = meta[5];
        float sy = __fsub_rn(ih, 1.0f);
        float sx = __fsub_rn(iw, 1.0f);
        const float* mb = meta + (size_t)b * METAS;
        float wy1 = __fsub_rn(mb[7], 0.0f) / sy;
        float wx1 = __fsub_rn(mb[8], 0.0f) / sx;
        float wy2 = __fsub_rn(mb[9], 1.0f) / sy;
        float wx2 = __fsub_rn(mb[10], 1.0f) / sx;

        // refine + clip (exact reference ops, no FMA contraction)
        float4 rv = ((const float4*)rois)[roi];
        float4 dv = ((const float4*)bbox)[(size_t)roi * CC + cls];
        float dy = __fmul_rn(dv.x, 0.1f);
        float dx = __fmul_rn(dv.y, 0.1f);
        float dh = __fmul_rn(dv.z, 0.2f);
        float dw = __fmul_rn(dv.w, 0.2f);
        float h = __fsub_rn(rv.z, rv.x);
        float w = __fsub_rn(rv.w, rv.y);
        float cy = __fadd_rn(__fadd_rn(rv.x, __fmul_rn(0.5f, h)), __fmul_rn(dy, h));
        float cx = __fadd_rn(__fadd_rn(rv.y, __fmul_rn(0.5f, w)), __fmul_rn(dx, w));
        float nh = __fmul_rn(h, expf(dh));
        float nw = __fmul_rn(w, expf(dw));
        float oy1 = fminf(fmaxf(__fsub_rn(cy, __fmul_rn(0.5f, nh)), wy1), wy2);
        float ox1 = fminf(fmaxf(__fsub_rn(cx, __fmul_rn(0.5f, nw)), wx1), wx2);
        float oy2 = fminf(fmaxf(__fadd_rn(cy, __fmul_rn(0.5f, nh)), wy1), wy2);
        float ox2 = fminf(fmaxf(__fadd_rn(cx, __fmul_rn(0.5f, nw)), wx1), wx2);

        float off = __fmul_rn(4.0f, (float)cls);
        g_rbox[roi] = make_float4(oy1, ox1, oy2, ox2);
        g_obox[roi] = make_float4(__fadd_rn(oy1, off), __fadd_rn(ox1, off),
                                  __fadd_rn(oy2, off), __fadd_rn(ox2, off));
        g_cls[roi] = cls;

        bool valid = (cls > 0) && (score >= 0.7f);
        if (valid) {
            unsigned int sb = __float_as_uint(score);
            u64 key = ((u64)sb << 11) | (u64)(2047 - n);   // score desc, idx asc
            int bk = b * CC + cls;
            int pos = atomicAdd(&g_bcnt[bk], 1);
            g_bucket[(size_t)bk * BCAP + pos] = key;
        }
    }
}

__device__ __forceinline__ float iou_ref(float4 bi, float ai, float4 bj) {
    float iy = fmaxf(0.0f, __fsub_rn(fminf(bi.z, bj.z), fmaxf(bi.x, bj.x)));
    float ix = fmaxf(0.0f, __fsub_rn(fminf(bi.w, bj.w), fmaxf(bi.y, bj.y)));
    float inter = __fmul_rn(iy, ix);
    float aj = __fmul_rn(__fsub_rn(bj.z, bj.x), __fsub_rn(bj.w, bj.y));
    float den = __fadd_rn(__fsub_rn(__fadd_rn(ai, aj), inter), 1e-12f);
    return inter / den;
}

// ===== Kernel 2: one warp per (image, class) bucket — full-chip NMS =====
// Cross-class IoU is exactly 0 (class offset 4*cls, boxes in [0,1]), so the
// global greedy NMS decomposes into independent per-class greedy NMS, and
// the per-class rank cap folds into a kept counter.
__global__ void __launch_bounds__(256)
nms_kernel() {
    const int lane = threadIdx.x & 31;
    const int b = threadIdx.x >> 5;       // 8 warps = 8 images
    const int c = blockIdx.x;             // 81 blocks = 81 classes
    const int bk = b * CC + c;

    if (c == 0) { if (lane == 0) g_kc[bk] = 0; return; }   // class 0 never valid
    const int L = g_bcnt[bk];
    if (L == 0) { if (lane == 0) g_kc[bk] = 0; return; }

    u64* bucket = g_bucket + (size_t)bk * BCAP;
    u64* keptp = g_keptbc + (size_t)bk * 128;
    const float4* obox = g_obox + b * NN;
    int keptc = 0;

    if (L <= 32) {
        // ---- register path: 1 key per lane, shfl bitonic, ballot greedy ----
        u64 key = (lane < L) ? bucket[lane] : 0ull;
        u64 v = ~key;   // ascending on ~key == descending on key; pads last
#pragma unroll
        for (int k = 2; k <= 32; k <<= 1) {
#pragma unroll
            for (int j = k >> 1; j > 0; j >>= 1) {
                u64 x = __shfl_xor_sync(FULLM, v, j);
                bool dir = ((lane & k) == 0);
                bool lower = ((lane & j) == 0);
                u64 mn = (v < x) ? v : x;
                u64 mx = (v < x) ? x : v;
                v = (dir == lower) ? mn : mx;
            }
        }
        key = ~v;   // lane i holds i-th largest key; lanes >= L hold 0

        float4 bx = make_float4(0.f, 0.f, 0.f, 0.f);
        float ar = 0.f;
        if (key != 0ull) {
            int orig = 2047 - (int)(key & 2047ull);
            bx = obox[orig];
            ar = __fmul_rn(__fsub_rn(bx.z, bx.x), __fsub_rn(bx.w, bx.y));
        }
        unsigned int alive = __ballot_sync(FULLM, key != 0ull);
        while (alive) {
            int a = __ffs(alive) - 1;                 // max remaining (sorted)
            u64 mk = __shfl_sync(FULLM, key, a);
            float4 bi;
            bi.x = __shfl_sync(FULLM, bx.x, a);
            bi.y = __shfl_sync(FULLM, bx.y, a);
            bi.z = __shfl_sync(FULLM, bx.z, a);
            bi.w = __shfl_sync(FULLM, bx.w, a);
            float ai = __shfl_sync(FULLM, ar, a);
            bool sup = false;
            if (((alive >> lane) & 1u) && lane > a)
                sup = iou_ref(bi, ai, bx) > 0.3f;
            unsigned int supm = __ballot_sync(FULLM, sup);
            alive &= ~supm;
            alive &= ~(1u << a);
            if (lane == 0 && keptc < MAXI) keptp[keptc] = mk;
            keptc++;
        }
    } else {
        // ---- rare fallback: odd-even sort (desc) in global + linear greedy ----
        for (int pass = 0; pass < L; pass++) {
            int start = pass & 1;
            for (int idx = start + 2 * lane; idx + 1 < L; idx += 64) {
                u64 a = bucket[idx], b2 = bucket[idx + 1];
                if (b2 > a) { bucket[idx] = b2; bucket[idx + 1] = a; }
            }
            __syncwarp();
        }
        for (int a = 0; a < L; a++) {
            u64 ka = bucket[a];
            if (!(ka & SUPBIT)) {
                int orig = 2047 - (int)(ka & 2047ull);
                float4 bi = obox[orig];
                float ai = __fmul_rn(__fsub_rn(bi.z, bi.x), __fsub_rn(bi.w, bi.y));
                for (int t = a + 1 + lane; t < L; t += 32) {
                    u64 kt = bucket[t];
                    if (!(kt & SUPBIT)) {
                        int oj = 2047 - (int)(kt & 2047ull);
                        if (iou_ref(bi, ai, obox[oj]) > 0.3f) bucket[t] = kt | SUPBIT;
                    }
                }
                if (lane == 0 && keptc < MAXI) keptp[keptc] = ka;
                keptc++;
            }
            __syncwarp();
        }
    }
    if (lane == 0) g_kc[bk] = (keptc < MAXI) ? keptc : MAXI;
}

// ===== Kernel 3: per-image compact + rank-select top-100 + write output =====
__global__ void __launch_bounds__(1024)
output_kernel(float* __restrict__ out) {
    __shared__ u64 sk[2048];
    __shared__ int skc[CC + 1], skb[CC + 1], sK;
    const int tid = threadIdx.x;
    const int lane = tid & 31;
    const int warp = tid >> 5;
    const int b = blockIdx.x;

    if (tid < CC) skc[tid] = g_kc[b * CC + tid];
    __syncthreads();

    if (warp == 0) {
        int run = 0;
        for (int cb = 0; cb < CC; cb += 32) {
            int c = cb + lane;
            int v = (c < CC) ? skc[c] : 0;
            int inc = v;
#pragma unroll
            for (int d = 1; d < 32; d <<= 1) {
                int u = __shfl_up_sync(FULLM, inc, d);
                if (lane >= d) inc += u;
            }
            if (c < CC) skb[c] = run + inc - v;
            run += __shfl_sync(FULLM, inc, 31);
        }
        if (lane == 0) sK = run;
    }
    __syncthreads();

    // compact kept keys into dense shared list
    for (int c = warp; c < CC; c += 32) {
        int kc = skc[c];
        int kb = skb[c];
        const u64* kp = g_keptbc + (size_t)(b * CC + c) * 128;
        for (int t = lane; t < kc; t += 32) sk[kb + t] = kp[t];
    }
    float* ob = out + (size_t)b * MAXI * 6;
    for (int x = tid; x < MAXI * 6; x += 1024) ob[x] = 0.0f;
    __syncthreads();

    const int K = sK;
    for (int i = tid; i < K; i += 1024) {
        u64 kk = sk[i];
        int r = 0;
        int j = 0;
#pragma unroll 8
        for (; j + 8 <= K; j += 8) {
            r += (sk[j] > kk);     r += (sk[j + 1] > kk);
            r += (sk[j + 2] > kk); r += (sk[j + 3] > kk);
            r += (sk[j + 4] > kk); r += (sk[j + 5] > kk);
            r += (sk[j + 6] > kk); r += (sk[j + 7] > kk);
        }
        for (; j < K; j++) r += (sk[j] > kk);
        if (r < MAXI) {
            int orig = 2047 - (int)(kk & 2047ull);
            float4 rb = g_rbox[b * NN + orig];
            float* o = ob + r * 6;
            o[0] = rb.x; o[1] = rb.y; o[2] = rb.z; o[3] = rb.w;
            o[4] = (float)g_cls[b * NN + orig];
            o[5] = __uint_as_float((unsigned int)(kk >> 11));
        }
    }
}

extern "C" void kernel_launch(void* const* d_in, const int* in_sizes, int n_in,
                              void* d_out, int out_size) {
    const float* rois  = (const float*)d_in[0];
    const float* probs = (const float*)d_in[1];
    const float* bbox  = (const float*)d_in[2];
    const float* meta  = (const float*)d_in[3];
    float* out = (float*)d_out;

    void* bcnt_ptr = nullptr;
    cudaGetSymbolAddress(&bcnt_ptr, g_bcnt);
    cudaMemsetAsync(bcnt_ptr, 0, NBKT * sizeof(int));

    prep_kernel<<<(BB * NN + 7) / 8, 256>>>(rois, probs, bbox, meta);
    nms_kernel<<<CC, 256>>>();
    output_kernel<<<BB, 1024>>>(out);
}